// round 7
// baseline (speedup 1.0000x reference)
#include <cuda_runtime.h>
#include <math.h>
#include <stdint.h>

#define B_ 2
#define T_ 2048
#define C_ 1024
#define H_ 16
#define DH_ 64
#define BT_ (B_*T_)
#define X_SIZE (BT_*C_)
#define ATT_SIZE (B_*H_*T_*T_)

// Scratch (device globals: allocation-free per harness rules)
__device__ float g_h[BT_ * C_];
__device__ float g_qkv[BT_ * 3 * C_];
__device__ float g_y[BT_ * C_];
__device__ float g_x1[BT_ * C_];
__device__ float g_m[BT_ * 4 * C_];
// tf32-rounded weights
__device__ float g_wattn[C_ * 3 * C_];
__device__ float g_wo[C_ * C_];
__device__ float g_wfc[C_ * 4 * C_];
__device__ float g_wfc2[4 * C_ * C_];

// ---------------------------------------------------------------------------
__device__ __forceinline__ uint32_t f2tf(float f) {
    uint32_t u;
    asm("cvt.rna.tf32.f32 %0, %1;" : "=r"(u) : "f"(f));
    return u;
}
__device__ __forceinline__ float f2tf_f(float f) { return __uint_as_float(f2tf(f)); }

__device__ __forceinline__ void mma_tf32(float (&d)[4], const uint32_t (&a)[4],
                                         const uint32_t (&b)[2]) {
    asm volatile(
        "mma.sync.aligned.m16n8k8.row.col.f32.tf32.tf32.f32 "
        "{%0,%1,%2,%3}, {%4,%5,%6,%7}, {%8,%9}, {%0,%1,%2,%3};"
        : "+f"(d[0]), "+f"(d[1]), "+f"(d[2]), "+f"(d[3])
        : "r"(a[0]), "r"(a[1]), "r"(a[2]), "r"(a[3]), "r"(b[0]), "r"(b[1]));
}

__device__ __forceinline__ void cp16(uint32_t dst, const float* src) {
    asm volatile("cp.async.cg.shared.global [%0], [%1], 16;" :: "r"(dst), "l"(src));
}
#define CP_COMMIT() asm volatile("cp.async.commit_group;")
#define CP_WAIT(n)  asm volatile("cp.async.wait_group %0;" :: "n"(n))

// ---------------------------------------------------------------------------
// Pre-round all 4 weight matrices to tf32 (rna) in one kernel.
// ---------------------------------------------------------------------------
#define N4_WA 786432
#define N4_WO 262144
#define N4_WF 1048576
#define N4_WF2 1048576
#define N4_TOT (N4_WA + N4_WO + N4_WF + N4_WF2)

__global__ void __launch_bounds__(256) cvt_all_kernel(
    const float4* __restrict__ wa_s, const float4* __restrict__ wo_s,
    const float4* __restrict__ wf_s, const float4* __restrict__ wf2_s,
    float4* __restrict__ wa_d, float4* __restrict__ wo_d,
    float4* __restrict__ wf_d, float4* __restrict__ wf2_d)
{
    int i = blockIdx.x * 256 + threadIdx.x;
    int stride = gridDim.x * 256;
    for (; i < N4_TOT; i += stride) {
        const float4* s; float4* d; int j = i;
        if (j < N4_WA)                { s = wa_s;  d = wa_d; }
        else if ((j -= N4_WA) < N4_WO)  { s = wo_s;  d = wo_d; }
        else if ((j -= N4_WO) < N4_WF)  { s = wf_s;  d = wf_d; }
        else { j -= N4_WF;              s = wf2_s; d = wf2_d; }
        float4 v = s[j];
        v.x = f2tf_f(v.x); v.y = f2tf_f(v.y); v.z = f2tf_f(v.z); v.w = f2tf_f(v.w);
        d[j] = v;
    }
}

// ---------------------------------------------------------------------------
// LayerNorm (outputs tf32-rna rounded).
// ---------------------------------------------------------------------------
__global__ void __launch_bounds__(256) ln_kernel(const float* __restrict__ x,
                                                 const float* __restrict__ g,
                                                 const float* __restrict__ be,
                                                 float* __restrict__ out)
{
    int row = blockIdx.x;
    int tid = threadIdx.x;
    const float4* xr = (const float4*)(x + (size_t)row * C_);
    float4 v = xr[tid];
    float s  = v.x + v.y + v.z + v.w;
    float ss = v.x * v.x + v.y * v.y + v.z * v.z + v.w * v.w;
    #pragma unroll
    for (int m = 16; m; m >>= 1) {
        s  += __shfl_xor_sync(0xffffffffu, s,  m);
        ss += __shfl_xor_sync(0xffffffffu, ss, m);
    }
    __shared__ float sh_s[8], sh_ss[8];
    if ((tid & 31) == 0) { sh_s[tid >> 5] = s; sh_ss[tid >> 5] = ss; }
    __syncthreads();
    s = 0.f; ss = 0.f;
    #pragma unroll
    for (int i = 0; i < 8; i++) { s += sh_s[i]; ss += sh_ss[i]; }
    float mean = s * (1.f / C_);
    float var  = ss * (1.f / C_) - mean * mean;
    float rstd = rsqrtf(var + 1e-5f);
    float4 gg = ((const float4*)g)[tid];
    float4 bb = ((const float4*)be)[tid];
    float4 o;
    o.x = f2tf_f((v.x - mean) * rstd * gg.x + bb.x);
    o.y = f2tf_f((v.y - mean) * rstd * gg.y + bb.y);
    o.z = f2tf_f((v.z - mean) * rstd * gg.z + bb.z);
    o.w = f2tf_f((v.w - mean) * rstd * gg.w + bb.w);
    ((float4*)(out + (size_t)row * C_))[tid] = o;
}

// ---------------------------------------------------------------------------
// tf32 tensor-core GEMM, cp.async 3-stage pipeline, BK=32, 2 CTAs/SM.
// ---------------------------------------------------------------------------
#define ASTR 36
#define BSTR 136
#define A_STG (128 * ASTR)
#define B_STG (32 * BSTR)
#define NSTAGE 3
#define GEMM_SMEM_BYTES (NSTAGE * (A_STG + B_STG) * 4)

template <int EPI>
__global__ void __launch_bounds__(256, 2) gemm_tc(
    const float* __restrict__ A, const float* __restrict__ W,
    const float* __restrict__ bias, const float* __restrict__ R,
    float* __restrict__ Cout, int M, int N, int K)
{
    extern __shared__ float dsm[];
    float* sA = dsm;
    float* sB = dsm + NSTAGE * A_STG;
    uint32_t sA_u = (uint32_t)__cvta_generic_to_shared(sA);
    uint32_t sB_u = (uint32_t)__cvta_generic_to_shared(sB);

    const int tid  = threadIdx.x;
    const int lane = tid & 31;
    const int wid  = tid >> 5;
    const int wm   = (wid >> 2) * 64;
    const int wn   = (wid & 3) * 32;
    const int m0 = blockIdx.y * 128, n0 = blockIdx.x * 128;
    const int gr = lane >> 2, gc = lane & 3;

    float acc[4][4][4];
    #pragma unroll
    for (int mt = 0; mt < 4; mt++)
        #pragma unroll
        for (int nt = 0; nt < 4; nt++)
            #pragma unroll
            for (int i = 0; i < 4; i++) acc[mt][nt][i] = 0.f;

    const int KT = K >> 5;   // BK = 32

    auto issue = [&](int kt, int s) {
        #pragma unroll
        for (int i = 0; i < 4; i++) {
            int id = tid + i * 256;
            int row = id >> 3, c4 = id & 7;
            cp16(sA_u + (uint32_t)(s * A_STG + row * ASTR + c4 * 4) * 4,
                 A + (size_t)(m0 + row) * K + kt * 32 + c4 * 4);
        }
        #pragma unroll
        for (int i = 0; i < 4; i++) {
            int id = tid + i * 256;
            int row = id >> 5, c4 = id & 31;
            cp16(sB_u + (uint32_t)(s * B_STG + row * BSTR + c4 * 4) * 4,
                 W + (size_t)(kt * 32 + row) * N + n0 + c4 * 4);
        }
    };

    issue(0, 0); CP_COMMIT();
    if (KT > 1) issue(1, 1);
    CP_COMMIT();
    CP_WAIT(1);
    __syncthreads();

    int s = 0;
    for (int kt = 0; kt < KT; kt++) {
        const uint32_t* ua = (const uint32_t*)(sA + s * A_STG);
        const uint32_t* ub = (const uint32_t*)(sB + s * B_STG);
        #pragma unroll
        for (int ks = 0; ks < 32; ks += 8) {
            uint32_t af[4][4];
            #pragma unroll
            for (int mt = 0; mt < 4; mt++) {
                int mrow = wm + mt * 16 + gr;
                af[mt][0] = ua[(mrow)     * ASTR + ks + gc];
                af[mt][1] = ua[(mrow + 8) * ASTR + ks + gc];
                af[mt][2] = ua[(mrow)     * ASTR + ks + gc + 4];
                af[mt][3] = ua[(mrow + 8) * ASTR + ks + gc + 4];
            }
            uint32_t bf[4][2];
            #pragma unroll
            for (int nt = 0; nt < 4; nt++) {
                int ncol = wn + nt * 8 + gr;
                bf[nt][0] = ub[(ks + gc)     * BSTR + ncol];
                bf[nt][1] = ub[(ks + gc + 4) * BSTR + ncol];
            }
            #pragma unroll
            for (int mt = 0; mt < 4; mt++)
                #pragma unroll
                for (int nt = 0; nt < 4; nt++)
                    mma_tf32(acc[mt][nt], af[mt], bf[nt]);
        }
        int kn = kt + 2;
        int sn = s + 2; if (sn >= NSTAGE) sn -= NSTAGE;
        if (kn < KT) issue(kn, sn);
        CP_COMMIT();
        CP_WAIT(1);
        __syncthreads();
        if (++s == NSTAGE) s = 0;
    }

    // ---- epilogue ----
    #pragma unroll
    for (int nt = 0; nt < 4; nt++) {
        int col = n0 + wn + nt * 8 + (gc << 1);
        float bx = bias[col], by = bias[col + 1];
        #pragma unroll
        for (int mt = 0; mt < 4; mt++) {
            int row0 = m0 + wm + mt * 16 + gr;
            #pragma unroll
            for (int half = 0; half < 2; half++) {
                int row = row0 + half * 8;
                float vx = acc[mt][nt][half * 2 + 0] + bx;
                float vy = acc[mt][nt][half * 2 + 1] + by;
                if (EPI == 2) {
                    vx = f2tf_f(0.5f * vx * (1.0f + erff(vx * 0.70710678118654752f)));
                    vy = f2tf_f(0.5f * vy * (1.0f + erff(vy * 0.70710678118654752f)));
                }
                size_t off = (size_t)row * N + col;
                if (EPI == 1) {
                    vx += R[off];
                    vy += R[off + 1];
                }
                *(float2*)(Cout + off) = make_float2(vx, vy);
            }
        }
    }
}

// ---------------------------------------------------------------------------
// Tensor-core causal flash attention, exact 2-pass softmax.
// CTA: 256 threads (8 warps), q-tile 128, k-tile 64. 2 CTAs/SM.
// Warp w owns q rows [16w, 16w+16). K/V loads shared by all 8 warps.
// Q/K/V raw fp32 bits into mma (HW tf32 truncation); P rna-rounded.
// ---------------------------------------------------------------------------
#define PAD 68
#define QROWS 128
#define ATTN_SMEM_BYTES ((QROWS + 64 + 64 + QROWS) * PAD * 4)

__global__ void __launch_bounds__(256, 2) attn_tc(
    const float* __restrict__ qkv, float* __restrict__ att,
    float* __restrict__ y, int write_att)
{
    extern __shared__ uint32_t sm[];
    uint32_t* Qs = sm;                    // [128][68]
    uint32_t* Ks = Qs + QROWS * PAD;      // [64][68]
    uint32_t* Vs = Ks + 64 * PAD;         // [64][68]
    uint32_t* Ps = Vs + 64 * PAD;         // [128][68]

    const int qt = gridDim.x - 1 - blockIdx.x;   // heaviest tiles first
    const int bh = blockIdx.y;
    const int b = bh >> 4, h = bh & 15;
    const int tid = threadIdx.x;
    const int lane = tid & 31, w = tid >> 5;
    const int gr = lane >> 2, gc = lane & 3;
    const int q0 = qt * QROWS;
    const int rs = 3 * C_;
    const float* base = qkv + (size_t)b * T_ * rs + h * DH_;
    const float scale = 0.125f;
    const int NKT = 2 * qt + 2;                  // valid k-tiles

    // ---- load Q tile: 128 rows x 64 d ----
    #pragma unroll
    for (int rr = 0; rr < 8; rr++) {
        int lin = tid + rr * 256;
        int row = lin >> 4, d4 = (lin & 15) * 4;
        float4 v = *(const float4*)(base + (size_t)(q0 + row) * rs + d4);
        *(uint4*)&Qs[row * PAD + d4] = *(uint4*)&v;
    }
    __syncthreads();

    const int mrowA = w * 16 + gr;

    float m0 = -1e30f, m1 = -1e30f, l0 = 0.f, l1 = 0.f;

    // ================= PASS 1: row statistics =================
    for (int kt = 0; kt < NKT; kt++) {
        #pragma unroll
        for (int rr = 0; rr < 4; rr++) {
            int lin = tid + rr * 256;
            int row = lin >> 4, d4 = (lin & 15) * 4;
            float4 v = *(const float4*)(base + C_ + (size_t)(kt * 64 + row) * rs + d4);
            *(uint4*)&Ks[row * PAD + d4] = *(uint4*)&v;
        }
        __syncthreads();

        float sf[8][4];
        #pragma unroll
        for (int nf = 0; nf < 8; nf++)
            #pragma unroll
            for (int i = 0; i < 4; i++) sf[nf][i] = 0.f;

        #pragma unroll
        for (int ks = 0; ks < 64; ks += 8) {
            uint32_t af[4];
            af[0] = Qs[(mrowA)     * PAD + ks + gc];
            af[1] = Qs[(mrowA + 8) * PAD + ks + gc];
            af[2] = Qs[(mrowA)     * PAD + ks + gc + 4];
            af[3] = Qs[(mrowA + 8) * PAD + ks + gc + 4];
            #pragma unroll
            for (int nf = 0; nf < 8; nf++) {
                uint32_t bf[2];
                bf[0] = Ks[(nf * 8 + gr) * PAD + ks + gc];
                bf[1] = Ks[(nf * 8 + gr) * PAD + ks + gc + 4];
                mma_tf32(sf[nf], af, bf);
            }
        }

        bool edge = (kt >= 2 * qt);
        int off = kt * 64 - q0;                 // valid only when edge
        #pragma unroll
        for (int nf = 0; nf < 8; nf++)
            #pragma unroll
            for (int i = 0; i < 4; i++) {
                float v = sf[nf][i] * scale;
                int ml = w * 16 + gr + ((i >= 2) ? 8 : 0);
                int nl = nf * 8 + 2 * gc + (i & 1);
                if (edge && (off + nl > ml)) v = -1e30f;
                sf[nf][i] = v;
            }

        float tm0 = -1e30f, tm1 = -1e30f;
        #pragma unroll
        for (int nf = 0; nf < 8; nf++) {
            tm0 = fmaxf(tm0, fmaxf(sf[nf][0], sf[nf][1]));
            tm1 = fmaxf(tm1, fmaxf(sf[nf][2], sf[nf][3]));
        }
        tm0 = fmaxf(tm0, __shfl_xor_sync(0xffffffffu, tm0, 1));
        tm0 = fmaxf(tm0, __shfl_xor_sync(0xffffffffu, tm0, 2));
        tm1 = fmaxf(tm1, __shfl_xor_sync(0xffffffffu, tm1, 1));
        tm1 = fmaxf(tm1, __shfl_xor_sync(0xffffffffu, tm1, 2));
        float mn0 = fmaxf(m0, tm0), mn1 = fmaxf(m1, tm1);
        float s0 = 0.f, s1 = 0.f;
        #pragma unroll
        for (int nf = 0; nf < 8; nf++) {
            s0 += __expf(sf[nf][0] - mn0) + __expf(sf[nf][1] - mn0);
            s1 += __expf(sf[nf][2] - mn1) + __expf(sf[nf][3] - mn1);
        }
        s0 += __shfl_xor_sync(0xffffffffu, s0, 1);
        s0 += __shfl_xor_sync(0xffffffffu, s0, 2);
        s1 += __shfl_xor_sync(0xffffffffu, s1, 1);
        s1 += __shfl_xor_sync(0xffffffffu, s1, 2);
        l0 = l0 * __expf(m0 - mn0) + s0; m0 = mn0;
        l1 = l1 * __expf(m1 - mn1) + s1; m1 = mn1;
        __syncthreads();
    }

    float linv0 = 1.f / l0, linv1 = 1.f / l1;

    float yac[8][4];
    #pragma unroll
    for (int nf = 0; nf < 8; nf++)
        #pragma unroll
        for (int i = 0; i < 4; i++) yac[nf][i] = 0.f;

    // ================= PASS 2: att + y = P@V =================
    for (int kt = 0; kt < NKT; kt++) {
        #pragma unroll
        for (int rr = 0; rr < 4; rr++) {
            int lin = tid + rr * 256;
            int row = lin >> 4, d4 = (lin & 15) * 4;
            float4 vk = *(const float4*)(base + C_ + (size_t)(kt * 64 + row) * rs + d4);
            *(uint4*)&Ks[row * PAD + d4] = *(uint4*)&vk;
            float4 vv = *(const float4*)(base + 2 * C_ + (size_t)(kt * 64 + row) * rs + d4);
            *(uint4*)&Vs[row * PAD + d4] = *(uint4*)&vv;
        }
        __syncthreads();

        float sf[8][4];
        #pragma unroll
        for (int nf = 0; nf < 8; nf++)
            #pragma unroll
            for (int i = 0; i < 4; i++) sf[nf][i] = 0.f;

        #pragma unroll
        for (int ks = 0; ks < 64; ks += 8) {
            uint32_t af[4];
            af[0] = Qs[(mrowA)     * PAD + ks + gc];
            af[1] = Qs[(mrowA + 8) * PAD + ks + gc];
            af[2] = Qs[(mrowA)     * PAD + ks + gc + 4];
            af[3] = Qs[(mrowA + 8) * PAD + ks + gc + 4];
            #pragma unroll
            for (int nf = 0; nf < 8; nf++) {
                uint32_t bf[2];
                bf[0] = Ks[(nf * 8 + gr) * PAD + ks + gc];
                bf[1] = Ks[(nf * 8 + gr) * PAD + ks + gc + 4];
                mma_tf32(sf[nf], af, bf);
            }
        }

        bool edge = (kt >= 2 * qt);
        int off = kt * 64 - q0;
        #pragma unroll
        for (int nf = 0; nf < 8; nf++) {
            float p[4];
            #pragma unroll
            for (int i = 0; i < 4; i++) {
                int ml = w * 16 + gr + ((i >= 2) ? 8 : 0);
                int nl = nf * 8 + 2 * gc + (i & 1);
                float mm = (i >= 2) ? m1 : m0;
                float li = (i >= 2) ? linv1 : linv0;
                float pv = __expf(sf[nf][i] * scale - mm) * li;
                if (edge && (off + nl > ml)) pv = 0.f;
                p[i] = pv;
            }
            if (write_att) {
                size_t rb = ((size_t)bh * T_ + q0 + w * 16 + gr) * T_ + kt * 64 + nf * 8 + 2 * gc;
                __stcs((float2*)(att + rb),          make_float2(p[0], p[1]));
                __stcs((float2*)(att + rb + 8 * T_), make_float2(p[2], p[3]));
            }
            uint2 u0; u0.x = f2tf(p[0]); u0.y = f2tf(p[1]);
            uint2 u1; u1.x = f2tf(p[2]); u1.y = f2tf(p[3]);
            *(uint2*)&Ps[(w * 16 + gr)     * PAD + nf * 8 + 2 * gc] = u0;
            *(uint2*)&Ps[(w * 16 + gr + 8) * PAD + nf * 8 + 2 * gc] = u1;
        }
        __syncwarp();

        #pragma unroll
        for (int ks = 0; ks < 64; ks += 8) {
            uint32_t af[4];
            af[0] = Ps[(mrowA)     * PAD + ks + gc];
            af[1] = Ps[(mrowA + 8) * PAD + ks + gc];
            af[2] = Ps[(mrowA)     * PAD + ks + gc + 4];
            af[3] = Ps[(mrowA + 8) * PAD + ks + gc + 4];
            #pragma unroll
            for (int nf = 0; nf < 8; nf++) {
                uint32_t bf[2];
                bf[0] = Vs[(ks + gc)     * PAD + nf * 8 + gr];
                bf[1] = Vs[(ks + gc + 4) * PAD + nf * 8 + gr];
                mma_tf32(yac[nf], af, bf);
            }
        }
        __syncthreads();
    }

    // ---- zero-fill causal upper triangle ----
    if (write_att) {
        float4 z = make_float4(0.f, 0.f, 0.f, 0.f);
        for (int kt = NKT; kt < T_ / 64; kt++) {
            #pragma unroll
            for (int rr = 0; rr < 8; rr++) {
                int lin = tid + rr * 256;
                int row = lin >> 4, c4 = (lin & 15) * 4;
                __stcs((float4*)(att + ((size_t)bh * T_ + q0 + row) * T_ + kt * 64 + c4), z);
            }
        }
    }

    // ---- write y (tf32-rounded; feeds GEMM A operand) ----
    #pragma unroll
    for (int nf = 0; nf < 8; nf++) {
        size_t rb = ((size_t)b * T_ + q0 + w * 16 + gr) * C_ + h * DH_ + nf * 8 + 2 * gc;
        *(float2*)(y + rb)          = make_float2(f2tf_f(yac[nf][0]), f2tf_f(yac[nf][1]));
        *(float2*)(y + rb + 8 * C_) = make_float2(f2tf_f(yac[nf][2]), f2tf_f(yac[nf][3]));
    }
}

// ---------------------------------------------------------------------------
extern "C" void kernel_launch(void* const* d_in, const int* in_sizes, int n_in,
                              void* d_out, int out_size)
{
    (void)in_sizes; (void)n_in;
    const float* x      = (const float*)d_in[0];
    const float* W_attn = (const float*)d_in[1];
    const float* b_attn = (const float*)d_in[2];
    const float* W_o    = (const float*)d_in[3];
    const float* b_o    = (const float*)d_in[4];
    const float* W_fc   = (const float*)d_in[5];
    const float* b_fc   = (const float*)d_in[6];
    const float* W_fc2  = (const float*)d_in[7];
    const float* b_fc2  = (const float*)d_in[8];
    const float* g1     = (const float*)d_in[9];
    const float* be1    = (const float*)d_in[10];
    const float* g2     = (const float*)d_in[11];
    const float* be2    = (const float*)d_in[12];
    float* out = (float*)d_out;

    float *h, *qkv, *y, *x1, *m, *wa, *wo, *wf, *wf2;
    cudaGetSymbolAddress((void**)&h,   g_h);
    cudaGetSymbolAddress((void**)&qkv, g_qkv);
    cudaGetSymbolAddress((void**)&y,   g_y);
    cudaGetSymbolAddress((void**)&x1,  g_x1);
    cudaGetSymbolAddress((void**)&m,   g_m);
    cudaGetSymbolAddress((void**)&wa,  g_wattn);
    cudaGetSymbolAddress((void**)&wo,  g_wo);
    cudaGetSymbolAddress((void**)&wf,  g_wfc);
    cudaGetSymbolAddress((void**)&wf2, g_wfc2);

    int write_att = (out_size >= X_SIZE + ATT_SIZE) ? 1 : 0;
    float* att = out + X_SIZE;

    cudaFuncSetAttribute(gemm_tc<0>, cudaFuncAttributeMaxDynamicSharedMemorySize, GEMM_SMEM_BYTES);
    cudaFuncSetAttribute(gemm_tc<1>, cudaFuncAttributeMaxDynamicSharedMemorySize, GEMM_SMEM_BYTES);
    cudaFuncSetAttribute(gemm_tc<2>, cudaFuncAttributeMaxDynamicSharedMemorySize, GEMM_SMEM_BYTES);
    cudaFuncSetAttribute(attn_tc, cudaFuncAttributeMaxDynamicSharedMemorySize, ATTN_SMEM_BYTES);

    // 0. pre-round weights to tf32 (rna)
    cvt_all_kernel<<<1184, 256>>>((const float4*)W_attn, (const float4*)W_o,
                                  (const float4*)W_fc, (const float4*)W_fc2,
                                  (float4*)wa, (float4*)wo, (float4*)wf, (float4*)wf2);

    // 1. h = LN1(x)
    ln_kernel<<<BT_, 256>>>(x, g1, be1, h);
    // 2. qkv = h @ W_attn + b_attn
    gemm_tc<0><<<dim3(3 * C_ / 128, BT_ / 128), 256, GEMM_SMEM_BYTES>>>(h, wa, b_attn, nullptr, qkv, BT_, 3 * C_, C_);
    // 3. attention -> att (d_out) + y
    attn_tc<<<dim3(T_ / QROWS, B_ * H_), 256, ATTN_SMEM_BYTES>>>(qkv, att, y, write_att);
    // 4. x1 = x + y @ W_o + b_o
    gemm_tc<1><<<dim3(C_ / 128, BT_ / 128), 256, GEMM_SMEM_BYTES>>>(y, wo, b_o, x, x1, BT_, C_, C_);
    // 5. h = LN2(x1)
    ln_kernel<<<BT_, 256>>>(x1, g2, be2, h);
    // 6. m = gelu(h @ W_fc + b_fc)
    gemm_tc<2><<<dim3(4 * C_ / 128, BT_ / 128), 256, GEMM_SMEM_BYTES>>>(h, wf, b_fc, nullptr, m, BT_, 4 * C_, C_);
    // 7. out_x = x1 + m @ W_fc2 + b_fc2
    gemm_tc<1><<<dim3(C_ / 128, BT_ / 128), 256, GEMM_SMEM_BYTES>>>(m, wf2, b_fc2, x1, out, BT_, C_, 4 * C_);
}

// round 8
// speedup vs baseline: 1.1069x; 1.1069x over previous
#include <cuda_runtime.h>
#include <math.h>
#include <stdint.h>

#define B_ 2
#define T_ 2048
#define C_ 1024
#define H_ 16
#define DH_ 64
#define BT_ (B_*T_)
#define X_SIZE (BT_*C_)
#define ATT_SIZE (B_*H_*T_*T_)

// Scratch (device globals: allocation-free per harness rules)
__device__ float g_h[BT_ * C_];
__device__ float g_qkv[BT_ * 3 * C_];
__device__ float g_y[BT_ * C_];
__device__ float g_x1[BT_ * C_];
__device__ float g_m[BT_ * 4 * C_];
// tf32-rounded weights
__device__ float g_wattn[C_ * 3 * C_];
__device__ float g_wo[C_ * C_];
__device__ float g_wfc[C_ * 4 * C_];
__device__ float g_wfc2[4 * C_ * C_];

// ---------------------------------------------------------------------------
__device__ __forceinline__ uint32_t f2tf(float f) {
    uint32_t u;
    asm("cvt.rna.tf32.f32 %0, %1;" : "=r"(u) : "f"(f));
    return u;
}
__device__ __forceinline__ float f2tf_f(float f) { return __uint_as_float(f2tf(f)); }

__device__ __forceinline__ void mma_tf32(float (&d)[4], const uint32_t (&a)[4],
                                         const uint32_t (&b)[2]) {
    asm volatile(
        "mma.sync.aligned.m16n8k8.row.col.f32.tf32.tf32.f32 "
        "{%0,%1,%2,%3}, {%4,%5,%6,%7}, {%8,%9}, {%0,%1,%2,%3};"
        : "+f"(d[0]), "+f"(d[1]), "+f"(d[2]), "+f"(d[3])
        : "r"(a[0]), "r"(a[1]), "r"(a[2]), "r"(a[3]), "r"(b[0]), "r"(b[1]));
}

__device__ __forceinline__ void cp16(uint32_t dst, const float* src) {
    asm volatile("cp.async.cg.shared.global [%0], [%1], 16;" :: "r"(dst), "l"(src));
}
#define CP_COMMIT() asm volatile("cp.async.commit_group;")
#define CP_WAIT(n)  asm volatile("cp.async.wait_group %0;" :: "n"(n))

// ---------------------------------------------------------------------------
// Pre-round all 4 weight matrices to tf32 (rna) in one kernel.
// ---------------------------------------------------------------------------
#define N4_WA 786432
#define N4_WO 262144
#define N4_WF 1048576
#define N4_WF2 1048576
#define N4_TOT (N4_WA + N4_WO + N4_WF + N4_WF2)

__global__ void __launch_bounds__(256) cvt_all_kernel(
    const float4* __restrict__ wa_s, const float4* __restrict__ wo_s,
    const float4* __restrict__ wf_s, const float4* __restrict__ wf2_s,
    float4* __restrict__ wa_d, float4* __restrict__ wo_d,
    float4* __restrict__ wf_d, float4* __restrict__ wf2_d)
{
    int i = blockIdx.x * 256 + threadIdx.x;
    int stride = gridDim.x * 256;
    for (; i < N4_TOT; i += stride) {
        const float4* s; float4* d; int j = i;
        if (j < N4_WA)                { s = wa_s;  d = wa_d; }
        else if ((j -= N4_WA) < N4_WO)  { s = wo_s;  d = wo_d; }
        else if ((j -= N4_WO) < N4_WF)  { s = wf_s;  d = wf_d; }
        else { j -= N4_WF;              s = wf2_s; d = wf2_d; }
        float4 v = s[j];
        v.x = f2tf_f(v.x); v.y = f2tf_f(v.y); v.z = f2tf_f(v.z); v.w = f2tf_f(v.w);
        d[j] = v;
    }
}

// ---------------------------------------------------------------------------
// LayerNorm (outputs tf32-rna rounded).
// ---------------------------------------------------------------------------
__global__ void __launch_bounds__(256) ln_kernel(const float* __restrict__ x,
                                                 const float* __restrict__ g,
                                                 const float* __restrict__ be,
                                                 float* __restrict__ out)
{
    int row = blockIdx.x;
    int tid = threadIdx.x;
    const float4* xr = (const float4*)(x + (size_t)row * C_);
    float4 v = xr[tid];
    float s  = v.x + v.y + v.z + v.w;
    float ss = v.x * v.x + v.y * v.y + v.z * v.z + v.w * v.w;
    #pragma unroll
    for (int m = 16; m; m >>= 1) {
        s  += __shfl_xor_sync(0xffffffffu, s,  m);
        ss += __shfl_xor_sync(0xffffffffu, ss, m);
    }
    __shared__ float sh_s[8], sh_ss[8];
    if ((tid & 31) == 0) { sh_s[tid >> 5] = s; sh_ss[tid >> 5] = ss; }
    __syncthreads();
    s = 0.f; ss = 0.f;
    #pragma unroll
    for (int i = 0; i < 8; i++) { s += sh_s[i]; ss += sh_ss[i]; }
    float mean = s * (1.f / C_);
    float var  = ss * (1.f / C_) - mean * mean;
    float rstd = rsqrtf(var + 1e-5f);
    float4 gg = ((const float4*)g)[tid];
    float4 bb = ((const float4*)be)[tid];
    float4 o;
    o.x = f2tf_f((v.x - mean) * rstd * gg.x + bb.x);
    o.y = f2tf_f((v.y - mean) * rstd * gg.y + bb.y);
    o.z = f2tf_f((v.z - mean) * rstd * gg.z + bb.z);
    o.w = f2tf_f((v.w - mean) * rstd * gg.w + bb.w);
    ((float4*)(out + (size_t)row * C_))[tid] = o;
}

// ---------------------------------------------------------------------------
// tf32 tensor-core GEMM, cp.async 3-stage pipeline, BK=32, 2 CTAs/SM.
// ---------------------------------------------------------------------------
#define ASTR 36
#define BSTR 136
#define A_STG (128 * ASTR)
#define B_STG (32 * BSTR)
#define NSTAGE 3
#define GEMM_SMEM_BYTES (NSTAGE * (A_STG + B_STG) * 4)

template <int EPI>
__global__ void __launch_bounds__(256, 2) gemm_tc(
    const float* __restrict__ A, const float* __restrict__ W,
    const float* __restrict__ bias, const float* __restrict__ R,
    float* __restrict__ Cout, int M, int N, int K)
{
    extern __shared__ float dsm[];
    float* sA = dsm;
    float* sB = dsm + NSTAGE * A_STG;
    uint32_t sA_u = (uint32_t)__cvta_generic_to_shared(sA);
    uint32_t sB_u = (uint32_t)__cvta_generic_to_shared(sB);

    const int tid  = threadIdx.x;
    const int lane = tid & 31;
    const int wid  = tid >> 5;
    const int wm   = (wid >> 2) * 64;
    const int wn   = (wid & 3) * 32;
    const int m0 = blockIdx.y * 128, n0 = blockIdx.x * 128;
    const int gr = lane >> 2, gc = lane & 3;

    float acc[4][4][4];
    #pragma unroll
    for (int mt = 0; mt < 4; mt++)
        #pragma unroll
        for (int nt = 0; nt < 4; nt++)
            #pragma unroll
            for (int i = 0; i < 4; i++) acc[mt][nt][i] = 0.f;

    const int KT = K >> 5;   // BK = 32

    auto issue = [&](int kt, int s) {
        #pragma unroll
        for (int i = 0; i < 4; i++) {
            int id = tid + i * 256;
            int row = id >> 3, c4 = id & 7;
            cp16(sA_u + (uint32_t)(s * A_STG + row * ASTR + c4 * 4) * 4,
                 A + (size_t)(m0 + row) * K + kt * 32 + c4 * 4);
        }
        #pragma unroll
        for (int i = 0; i < 4; i++) {
            int id = tid + i * 256;
            int row = id >> 5, c4 = id & 31;
            cp16(sB_u + (uint32_t)(s * B_STG + row * BSTR + c4 * 4) * 4,
                 W + (size_t)(kt * 32 + row) * N + n0 + c4 * 4);
        }
    };

    issue(0, 0); CP_COMMIT();
    if (KT > 1) issue(1, 1);
    CP_COMMIT();
    CP_WAIT(1);
    __syncthreads();

    int s = 0;
    for (int kt = 0; kt < KT; kt++) {
        const uint32_t* ua = (const uint32_t*)(sA + s * A_STG);
        const uint32_t* ub = (const uint32_t*)(sB + s * B_STG);
        #pragma unroll
        for (int ks = 0; ks < 32; ks += 8) {
            uint32_t af[4][4];
            #pragma unroll
            for (int mt = 0; mt < 4; mt++) {
                int mrow = wm + mt * 16 + gr;
                af[mt][0] = ua[(mrow)     * ASTR + ks + gc];
                af[mt][1] = ua[(mrow + 8) * ASTR + ks + gc];
                af[mt][2] = ua[(mrow)     * ASTR + ks + gc + 4];
                af[mt][3] = ua[(mrow + 8) * ASTR + ks + gc + 4];
            }
            uint32_t bf[4][2];
            #pragma unroll
            for (int nt = 0; nt < 4; nt++) {
                int ncol = wn + nt * 8 + gr;
                bf[nt][0] = ub[(ks + gc)     * BSTR + ncol];
                bf[nt][1] = ub[(ks + gc + 4) * BSTR + ncol];
            }
            #pragma unroll
            for (int mt = 0; mt < 4; mt++)
                #pragma unroll
                for (int nt = 0; nt < 4; nt++)
                    mma_tf32(acc[mt][nt], af[mt], bf[nt]);
        }
        int kn = kt + 2;
        int sn = s + 2; if (sn >= NSTAGE) sn -= NSTAGE;
        if (kn < KT) issue(kn, sn);
        CP_COMMIT();
        CP_WAIT(1);
        __syncthreads();
        if (++s == NSTAGE) s = 0;
    }

    // ---- epilogue ----
    #pragma unroll
    for (int nt = 0; nt < 4; nt++) {
        int col = n0 + wn + nt * 8 + (gc << 1);
        float bx = bias[col], by = bias[col + 1];
        #pragma unroll
        for (int mt = 0; mt < 4; mt++) {
            int row0 = m0 + wm + mt * 16 + gr;
            #pragma unroll
            for (int half = 0; half < 2; half++) {
                int row = row0 + half * 8;
                float vx = acc[mt][nt][half * 2 + 0] + bx;
                float vy = acc[mt][nt][half * 2 + 1] + by;
                if (EPI == 2) {
                    vx = f2tf_f(0.5f * vx * (1.0f + erff(vx * 0.70710678118654752f)));
                    vy = f2tf_f(0.5f * vy * (1.0f + erff(vy * 0.70710678118654752f)));
                }
                size_t off = (size_t)row * N + col;
                if (EPI == 1) {
                    vx += R[off];
                    vy += R[off + 1];
                }
                *(float2*)(Cout + off) = make_float2(vx, vy);
            }
        }
    }
}

// ---------------------------------------------------------------------------
// Tensor-core causal flash attention, exact 2-pass softmax.
// CTA: 128 threads (4 warps), q-tile 64, k-tile 64. 4 CTAs/SM (52.2KB smem).
// Pass 1 ping-pongs K through the K/V buffers with cp.async (load overlaps mma).
// PV A-fragments come from softmax registers via intra-quad shuffle transpose
// (no P smem, no syncwarp).
// ---------------------------------------------------------------------------
#define PAD 68
#define ATTN_SMEM_BYTES (3 * 64 * PAD * 4)   // Q + 2 K/V buffers = 52224 B

__global__ void __launch_bounds__(128, 4) attn_tc(
    const float* __restrict__ qkv, float* __restrict__ att,
    float* __restrict__ y, int write_att)
{
    extern __shared__ uint32_t sm[];
    uint32_t* Qs = sm;                 // [64][68]
    uint32_t* B0 = Qs + 64 * PAD;      // K ping / K (pass2)
    uint32_t* B1 = B0 + 64 * PAD;      // K pong / V (pass2)

    const int qt = gridDim.x - 1 - blockIdx.x;   // heaviest tiles first
    const int bh = blockIdx.y;
    const int b = bh >> 4, h = bh & 15;
    const int tid = threadIdx.x;
    const int lane = tid & 31, w = tid >> 5;
    const int gr = lane >> 2, gc = lane & 3;
    const int q0 = qt * 64;
    const int rs = 3 * C_;
    const float* base = qkv + (size_t)b * T_ * rs + h * DH_;
    const float scale = 0.125f;

    // cp.async tile loaders: 64 rows x 64 floats, 8 cp16 per thread
    auto issueT = [&](const float* src_base, int kt, uint32_t* buf) {
        uint32_t bu = (uint32_t)__cvta_generic_to_shared(buf);
        #pragma unroll
        for (int i = 0; i < 8; i++) {
            int id = tid + i * 128;
            int row = id >> 4, c4 = id & 15;
            cp16(bu + (uint32_t)(row * PAD + c4 * 4) * 4,
                 src_base + (size_t)(kt * 64 + row) * rs + c4 * 4);
        }
    };

    // ---- load Q tile ----
    #pragma unroll
    for (int rr = 0; rr < 4; rr++) {
        int lin = tid + rr * 128;
        int row = lin >> 3, d4 = (lin & 7) * 8;
        float4 v0 = *(const float4*)(base + (size_t)(q0 + row) * rs + d4);
        float4 v1 = *(const float4*)(base + (size_t)(q0 + row) * rs + d4 + 4);
        *(uint4*)&Qs[row * PAD + d4]     = *(uint4*)&v0;
        *(uint4*)&Qs[row * PAD + d4 + 4] = *(uint4*)&v1;
    }

    const int mrowA = w * 16 + gr;
    float m0 = -1e30f, m1 = -1e30f, l0 = 0.f, l1 = 0.f;

    // ================= PASS 1: row statistics =================
    issueT(base + C_, 0, B0); CP_COMMIT(); CP_WAIT(0);
    __syncthreads();

    for (int kt = 0; kt <= qt; kt++) {
        const uint32_t* kb = (kt & 1) ? B1 : B0;
        if (kt < qt) { issueT(base + C_, kt + 1, (kt & 1) ? B0 : B1); CP_COMMIT(); }

        float sf[8][4];
        #pragma unroll
        for (int nf = 0; nf < 8; nf++)
            #pragma unroll
            for (int i = 0; i < 4; i++) sf[nf][i] = 0.f;

        #pragma unroll
        for (int ks = 0; ks < 64; ks += 8) {
            uint32_t af[4];
            af[0] = Qs[(mrowA)     * PAD + ks + gc];
            af[1] = Qs[(mrowA + 8) * PAD + ks + gc];
            af[2] = Qs[(mrowA)     * PAD + ks + gc + 4];
            af[3] = Qs[(mrowA + 8) * PAD + ks + gc + 4];
            #pragma unroll
            for (int nf = 0; nf < 8; nf++) {
                uint32_t bf[2];
                bf[0] = kb[(nf * 8 + gr) * PAD + ks + gc];
                bf[1] = kb[(nf * 8 + gr) * PAD + ks + gc + 4];
                mma_tf32(sf[nf], af, bf);
            }
        }

        bool diag = (kt == qt);
        #pragma unroll
        for (int nf = 0; nf < 8; nf++)
            #pragma unroll
            for (int i = 0; i < 4; i++) {
                float v = sf[nf][i] * scale;
                int ml = w * 16 + gr + ((i >= 2) ? 8 : 0);
                int nl = nf * 8 + 2 * gc + (i & 1);
                if (diag && nl > ml) v = -1e30f;
                sf[nf][i] = v;
            }

        float tm0 = -1e30f, tm1 = -1e30f;
        #pragma unroll
        for (int nf = 0; nf < 8; nf++) {
            tm0 = fmaxf(tm0, fmaxf(sf[nf][0], sf[nf][1]));
            tm1 = fmaxf(tm1, fmaxf(sf[nf][2], sf[nf][3]));
        }
        tm0 = fmaxf(tm0, __shfl_xor_sync(0xffffffffu, tm0, 1));
        tm0 = fmaxf(tm0, __shfl_xor_sync(0xffffffffu, tm0, 2));
        tm1 = fmaxf(tm1, __shfl_xor_sync(0xffffffffu, tm1, 1));
        tm1 = fmaxf(tm1, __shfl_xor_sync(0xffffffffu, tm1, 2));
        float mn0 = fmaxf(m0, tm0), mn1 = fmaxf(m1, tm1);
        float s0 = 0.f, s1 = 0.f;
        #pragma unroll
        for (int nf = 0; nf < 8; nf++) {
            s0 += __expf(sf[nf][0] - mn0) + __expf(sf[nf][1] - mn0);
            s1 += __expf(sf[nf][2] - mn1) + __expf(sf[nf][3] - mn1);
        }
        s0 += __shfl_xor_sync(0xffffffffu, s0, 1);
        s0 += __shfl_xor_sync(0xffffffffu, s0, 2);
        s1 += __shfl_xor_sync(0xffffffffu, s1, 1);
        s1 += __shfl_xor_sync(0xffffffffu, s1, 2);
        l0 = l0 * __expf(m0 - mn0) + s0; m0 = mn0;
        l1 = l1 * __expf(m1 - mn1) + s1; m1 = mn1;

        CP_WAIT(0);
        __syncthreads();
    }

    float linv0 = 1.f / l0, linv1 = 1.f / l1;

    float yac[8][4];
    #pragma unroll
    for (int nf = 0; nf < 8; nf++)
        #pragma unroll
        for (int i = 0; i < 4; i++) yac[nf][i] = 0.f;

    // ================= PASS 2: att + y = P@V =================
    for (int kt = 0; kt <= qt; kt++) {
        issueT(base + C_,     kt, B0);   // K
        issueT(base + 2 * C_, kt, B1);   // V
        CP_COMMIT(); CP_WAIT(0);
        __syncthreads();

        float sf[8][4];
        #pragma unroll
        for (int nf = 0; nf < 8; nf++)
            #pragma unroll
            for (int i = 0; i < 4; i++) sf[nf][i] = 0.f;

        #pragma unroll
        for (int ks = 0; ks < 64; ks += 8) {
            uint32_t af[4];
            af[0] = Qs[(mrowA)     * PAD + ks + gc];
            af[1] = Qs[(mrowA + 8) * PAD + ks + gc];
            af[2] = Qs[(mrowA)     * PAD + ks + gc + 4];
            af[3] = Qs[(mrowA + 8) * PAD + ks + gc + 4];
            #pragma unroll
            for (int nf = 0; nf < 8; nf++) {
                uint32_t bf[2];
                bf[0] = B0[(nf * 8 + gr) * PAD + ks + gc];
                bf[1] = B0[(nf * 8 + gr) * PAD + ks + gc + 4];
                mma_tf32(sf[nf], af, bf);
            }
        }

        bool diag = (kt == qt);
        #pragma unroll
        for (int j = 0; j < 8; j++) {
            float p[4];
            #pragma unroll
            for (int i = 0; i < 4; i++) {
                int ml = w * 16 + gr + ((i >= 2) ? 8 : 0);
                int nl = j * 8 + 2 * gc + (i & 1);
                float mm = (i >= 2) ? m1 : m0;
                float li = (i >= 2) ? linv1 : linv0;
                float pv = __expf(sf[j][i] * scale - mm) * li;
                if (diag && nl > ml) pv = 0.f;
                p[i] = pv;
            }
            if (write_att) {
                size_t rb = ((size_t)bh * T_ + q0 + w * 16 + gr) * T_ + kt * 64 + j * 8 + 2 * gc;
                __stcs((float2*)(att + rb),          make_float2(p[0], p[1]));
                __stcs((float2*)(att + rb + 8 * T_), make_float2(p[2], p[3]));
            }
            // shuffle transpose: accumulator layout -> A-operand layout for chunk j
            int src0 = (lane & ~3) | (gc >> 1);
            float q0v = __shfl_sync(0xffffffffu, p[0], src0);
            float q1v = __shfl_sync(0xffffffffu, p[1], src0);
            float q2v = __shfl_sync(0xffffffffu, p[2], src0);
            float q3v = __shfl_sync(0xffffffffu, p[3], src0);
            float r0v = __shfl_sync(0xffffffffu, p[0], src0 + 2);
            float r1v = __shfl_sync(0xffffffffu, p[1], src0 + 2);
            float r2v = __shfl_sync(0xffffffffu, p[2], src0 + 2);
            float r3v = __shfl_sync(0xffffffffu, p[3], src0 + 2);
            bool odd = (gc & 1);
            uint32_t af[4];
            af[0] = __float_as_uint(odd ? q1v : q0v);   // (gr,   8j+gc)
            af[1] = __float_as_uint(odd ? q3v : q2v);   // (gr+8, 8j+gc)
            af[2] = __float_as_uint(odd ? r1v : r0v);   // (gr,   8j+gc+4)
            af[3] = __float_as_uint(odd ? r3v : r2v);   // (gr+8, 8j+gc+4)
            #pragma unroll
            for (int nf2 = 0; nf2 < 8; nf2++) {
                uint32_t bf[2];
                bf[0] = B1[(j * 8 + gc)     * PAD + nf2 * 8 + gr];
                bf[1] = B1[(j * 8 + gc + 4) * PAD + nf2 * 8 + gr];
                mma_tf32(yac[nf2], af, bf);
            }
        }
        __syncthreads();
    }

    // ---- zero-fill causal upper triangle ----
    if (write_att) {
        float4 z = make_float4(0.f, 0.f, 0.f, 0.f);
        for (int kt = qt + 1; kt < T_ / 64; kt++) {
            #pragma unroll
            for (int rr = 0; rr < 8; rr++) {
                int lin = tid + rr * 128;
                int row = lin >> 4, c4 = (lin & 15) * 4;
                __stcs((float4*)(att + ((size_t)bh * T_ + q0 + row) * T_ + kt * 64 + c4), z);
            }
        }
    }

    // ---- write y (tf32-rounded; feeds GEMM A operand) ----
    #pragma unroll
    for (int nf = 0; nf < 8; nf++) {
        size_t rb = ((size_t)b * T_ + q0 + w * 16 + gr) * C_ + h * DH_ + nf * 8 + 2 * gc;
        *(float2*)(y + rb)          = make_float2(f2tf_f(yac[nf][0]), f2tf_f(yac[nf][1]));
        *(float2*)(y + rb + 8 * C_) = make_float2(f2tf_f(yac[nf][2]), f2tf_f(yac[nf][3]));
    }
}

// ---------------------------------------------------------------------------
extern "C" void kernel_launch(void* const* d_in, const int* in_sizes, int n_in,
                              void* d_out, int out_size)
{
    (void)in_sizes; (void)n_in;
    const float* x      = (const float*)d_in[0];
    const float* W_attn = (const float*)d_in[1];
    const float* b_attn = (const float*)d_in[2];
    const float* W_o    = (const float*)d_in[3];
    const float* b_o    = (const float*)d_in[4];
    const float* W_fc   = (const float*)d_in[5];
    const float* b_fc   = (const float*)d_in[6];
    const float* W_fc2  = (const float*)d_in[7];
    const float* b_fc2  = (const float*)d_in[8];
    const float* g1     = (const float*)d_in[9];
    const float* be1    = (const float*)d_in[10];
    const float* g2     = (const float*)d_in[11];
    const float* be2    = (const float*)d_in[12];
    float* out = (float*)d_out;

    float *h, *qkv, *y, *x1, *m, *wa, *wo, *wf, *wf2;
    cudaGetSymbolAddress((void**)&h,   g_h);
    cudaGetSymbolAddress((void**)&qkv, g_qkv);
    cudaGetSymbolAddress((void**)&y,   g_y);
    cudaGetSymbolAddress((void**)&x1,  g_x1);
    cudaGetSymbolAddress((void**)&m,   g_m);
    cudaGetSymbolAddress((void**)&wa,  g_wattn);
    cudaGetSymbolAddress((void**)&wo,  g_wo);
    cudaGetSymbolAddress((void**)&wf,  g_wfc);
    cudaGetSymbolAddress((void**)&wf2, g_wfc2);

    int write_att = (out_size >= X_SIZE + ATT_SIZE) ? 1 : 0;
    float* att = out + X_SIZE;

    cudaFuncSetAttribute(gemm_tc<0>, cudaFuncAttributeMaxDynamicSharedMemorySize, GEMM_SMEM_BYTES);
    cudaFuncSetAttribute(gemm_tc<1>, cudaFuncAttributeMaxDynamicSharedMemorySize, GEMM_SMEM_BYTES);
    cudaFuncSetAttribute(gemm_tc<2>, cudaFuncAttributeMaxDynamicSharedMemorySize, GEMM_SMEM_BYTES);
    cudaFuncSetAttribute(attn_tc, cudaFuncAttributeMaxDynamicSharedMemorySize, ATTN_SMEM_BYTES);

    // 0. pre-round weights to tf32 (rna)
    cvt_all_kernel<<<1184, 256>>>((const float4*)W_attn, (const float4*)W_o,
                                  (const float4*)W_fc, (const float4*)W_fc2,
                                  (float4*)wa, (float4*)wo, (float4*)wf, (float4*)wf2);

    // 1. h = LN1(x)
    ln_kernel<<<BT_, 256>>>(x, g1, be1, h);
    // 2. qkv = h @ W_attn + b_attn
    gemm_tc<0><<<dim3(3 * C_ / 128, BT_ / 128), 256, GEMM_SMEM_BYTES>>>(h, wa, b_attn, nullptr, qkv, BT_, 3 * C_, C_);
    // 3. attention -> att (d_out) + y
    attn_tc<<<dim3(T_ / 64, B_ * H_), 128, ATTN_SMEM_BYTES>>>(qkv, att, y, write_att);
    // 4. x1 = x + y @ W_o + b_o
    gemm_tc<1><<<dim3(C_ / 128, BT_ / 128), 256, GEMM_SMEM_BYTES>>>(y, wo, b_o, x, x1, BT_, C_, C_);
    // 5. h = LN2(x1)
    ln_kernel<<<BT_, 256>>>(x1, g2, be2, h);
    // 6. m = gelu(h @ W_fc + b_fc)
    gemm_tc<2><<<dim3(4 * C_ / 128, BT_ / 128), 256, GEMM_SMEM_BYTES>>>(h, wf, b_fc, nullptr, m, BT_, 4 * C_, C_);
    // 7. out_x = x1 + m @ W_fc2 + b_fc2
    gemm_tc<1><<<dim3(C_ / 128, BT_ / 128), 256, GEMM_SMEM_BYTES>>>(m, wf2, b_fc2, x1, out, BT_, C_, 4 * C_);
}

// round 9
// speedup vs baseline: 1.1288x; 1.0198x over previous
#include <cuda_runtime.h>
#include <math.h>
#include <stdint.h>

#define B_ 2
#define T_ 2048
#define C_ 1024
#define H_ 16
#define DH_ 64
#define BT_ (B_*T_)
#define X_SIZE (BT_*C_)
#define ATT_SIZE (B_*H_*T_*T_)

// Scratch (device globals: allocation-free per harness rules)
__device__ float g_h[BT_ * C_];
__device__ float g_qkv[BT_ * 3 * C_];
__device__ float g_y[BT_ * C_];
__device__ float g_x1[BT_ * C_];
__device__ float g_m[BT_ * 4 * C_];
// tf32-rounded weights
__device__ float g_wattn[C_ * 3 * C_];
__device__ float g_wo[C_ * C_];
__device__ float g_wfc[C_ * 4 * C_];
__device__ float g_wfc2[4 * C_ * C_];

// ---------------------------------------------------------------------------
__device__ __forceinline__ uint32_t f2tf(float f) {
    uint32_t u;
    asm("cvt.rna.tf32.f32 %0, %1;" : "=r"(u) : "f"(f));
    return u;
}
__device__ __forceinline__ float f2tf_f(float f) { return __uint_as_float(f2tf(f)); }

__device__ __forceinline__ void mma_tf32(float (&d)[4], const uint32_t (&a)[4],
                                         const uint32_t (&b)[2]) {
    asm volatile(
        "mma.sync.aligned.m16n8k8.row.col.f32.tf32.tf32.f32 "
        "{%0,%1,%2,%3}, {%4,%5,%6,%7}, {%8,%9}, {%0,%1,%2,%3};"
        : "+f"(d[0]), "+f"(d[1]), "+f"(d[2]), "+f"(d[3])
        : "r"(a[0]), "r"(a[1]), "r"(a[2]), "r"(a[3]), "r"(b[0]), "r"(b[1]));
}

__device__ __forceinline__ void cp16(uint32_t dst, const float* src) {
    asm volatile("cp.async.cg.shared.global [%0], [%1], 16;" :: "r"(dst), "l"(src));
}
#define CP_COMMIT() asm volatile("cp.async.commit_group;")
#define CP_WAIT(n)  asm volatile("cp.async.wait_group %0;" :: "n"(n))

// ---------------------------------------------------------------------------
// Pre-round all 4 weight matrices to tf32 (rna) in one kernel.
// ---------------------------------------------------------------------------
#define N4_WA 786432
#define N4_WO 262144
#define N4_WF 1048576
#define N4_WF2 1048576
#define N4_TOT (N4_WA + N4_WO + N4_WF + N4_WF2)

__global__ void __launch_bounds__(256) cvt_all_kernel(
    const float4* __restrict__ wa_s, const float4* __restrict__ wo_s,
    const float4* __restrict__ wf_s, const float4* __restrict__ wf2_s,
    float4* __restrict__ wa_d, float4* __restrict__ wo_d,
    float4* __restrict__ wf_d, float4* __restrict__ wf2_d)
{
    int i = blockIdx.x * 256 + threadIdx.x;
    int stride = gridDim.x * 256;
    for (; i < N4_TOT; i += stride) {
        const float4* s; float4* d; int j = i;
        if (j < N4_WA)                { s = wa_s;  d = wa_d; }
        else if ((j -= N4_WA) < N4_WO)  { s = wo_s;  d = wo_d; }
        else if ((j -= N4_WO) < N4_WF)  { s = wf_s;  d = wf_d; }
        else { j -= N4_WF;              s = wf2_s; d = wf2_d; }
        float4 v = s[j];
        v.x = f2tf_f(v.x); v.y = f2tf_f(v.y); v.z = f2tf_f(v.z); v.w = f2tf_f(v.w);
        d[j] = v;
    }
}

// ---------------------------------------------------------------------------
// LayerNorm (outputs tf32-rna rounded).
// ---------------------------------------------------------------------------
__global__ void __launch_bounds__(256) ln_kernel(const float* __restrict__ x,
                                                 const float* __restrict__ g,
                                                 const float* __restrict__ be,
                                                 float* __restrict__ out)
{
    int row = blockIdx.x;
    int tid = threadIdx.x;
    const float4* xr = (const float4*)(x + (size_t)row * C_);
    float4 v = xr[tid];
    float s  = v.x + v.y + v.z + v.w;
    float ss = v.x * v.x + v.y * v.y + v.z * v.z + v.w * v.w;
    #pragma unroll
    for (int m = 16; m; m >>= 1) {
        s  += __shfl_xor_sync(0xffffffffu, s,  m);
        ss += __shfl_xor_sync(0xffffffffu, ss, m);
    }
    __shared__ float sh_s[8], sh_ss[8];
    if ((tid & 31) == 0) { sh_s[tid >> 5] = s; sh_ss[tid >> 5] = ss; }
    __syncthreads();
    s = 0.f; ss = 0.f;
    #pragma unroll
    for (int i = 0; i < 8; i++) { s += sh_s[i]; ss += sh_ss[i]; }
    float mean = s * (1.f / C_);
    float var  = ss * (1.f / C_) - mean * mean;
    float rstd = rsqrtf(var + 1e-5f);
    float4 gg = ((const float4*)g)[tid];
    float4 bb = ((const float4*)be)[tid];
    float4 o;
    o.x = f2tf_f((v.x - mean) * rstd * gg.x + bb.x);
    o.y = f2tf_f((v.y - mean) * rstd * gg.y + bb.y);
    o.z = f2tf_f((v.z - mean) * rstd * gg.z + bb.z);
    o.w = f2tf_f((v.w - mean) * rstd * gg.w + bb.w);
    ((float4*)(out + (size_t)row * C_))[tid] = o;
}

// ---------------------------------------------------------------------------
// tf32 tensor-core GEMM, cp.async 3-stage pipeline, BK=32, 2 CTAs/SM.
// ---------------------------------------------------------------------------
#define ASTR 36
#define BSTR 136
#define A_STG (128 * ASTR)
#define B_STG (32 * BSTR)
#define NSTAGE 3
#define GEMM_SMEM_BYTES (NSTAGE * (A_STG + B_STG) * 4)

template <int EPI>
__global__ void __launch_bounds__(256, 2) gemm_tc(
    const float* __restrict__ A, const float* __restrict__ W,
    const float* __restrict__ bias, const float* __restrict__ R,
    float* __restrict__ Cout, int M, int N, int K)
{
    extern __shared__ float dsm[];
    float* sA = dsm;
    float* sB = dsm + NSTAGE * A_STG;
    uint32_t sA_u = (uint32_t)__cvta_generic_to_shared(sA);
    uint32_t sB_u = (uint32_t)__cvta_generic_to_shared(sB);

    const int tid  = threadIdx.x;
    const int lane = tid & 31;
    const int wid  = tid >> 5;
    const int wm   = (wid >> 2) * 64;
    const int wn   = (wid & 3) * 32;
    const int m0 = blockIdx.y * 128, n0 = blockIdx.x * 128;
    const int gr = lane >> 2, gc = lane & 3;

    float acc[4][4][4];
    #pragma unroll
    for (int mt = 0; mt < 4; mt++)
        #pragma unroll
        for (int nt = 0; nt < 4; nt++)
            #pragma unroll
            for (int i = 0; i < 4; i++) acc[mt][nt][i] = 0.f;

    const int KT = K >> 5;   // BK = 32

    auto issue = [&](int kt, int s) {
        #pragma unroll
        for (int i = 0; i < 4; i++) {
            int id = tid + i * 256;
            int row = id >> 3, c4 = id & 7;
            cp16(sA_u + (uint32_t)(s * A_STG + row * ASTR + c4 * 4) * 4,
                 A + (size_t)(m0 + row) * K + kt * 32 + c4 * 4);
        }
        #pragma unroll
        for (int i = 0; i < 4; i++) {
            int id = tid + i * 256;
            int row = id >> 5, c4 = id & 31;
            cp16(sB_u + (uint32_t)(s * B_STG + row * BSTR + c4 * 4) * 4,
                 W + (size_t)(kt * 32 + row) * N + n0 + c4 * 4);
        }
    };

    issue(0, 0); CP_COMMIT();
    if (KT > 1) issue(1, 1);
    CP_COMMIT();
    CP_WAIT(1);
    __syncthreads();

    int s = 0;
    for (int kt = 0; kt < KT; kt++) {
        const uint32_t* ua = (const uint32_t*)(sA + s * A_STG);
        const uint32_t* ub = (const uint32_t*)(sB + s * B_STG);
        #pragma unroll
        for (int ks = 0; ks < 32; ks += 8) {
            uint32_t af[4][4];
            #pragma unroll
            for (int mt = 0; mt < 4; mt++) {
                int mrow = wm + mt * 16 + gr;
                af[mt][0] = ua[(mrow)     * ASTR + ks + gc];
                af[mt][1] = ua[(mrow + 8) * ASTR + ks + gc];
                af[mt][2] = ua[(mrow)     * ASTR + ks + gc + 4];
                af[mt][3] = ua[(mrow + 8) * ASTR + ks + gc + 4];
            }
            uint32_t bf[4][2];
            #pragma unroll
            for (int nt = 0; nt < 4; nt++) {
                int ncol = wn + nt * 8 + gr;
                bf[nt][0] = ub[(ks + gc)     * BSTR + ncol];
                bf[nt][1] = ub[(ks + gc + 4) * BSTR + ncol];
            }
            #pragma unroll
            for (int mt = 0; mt < 4; mt++)
                #pragma unroll
                for (int nt = 0; nt < 4; nt++)
                    mma_tf32(acc[mt][nt], af[mt], bf[nt]);
        }
        int kn = kt + 2;
        int sn = s + 2; if (sn >= NSTAGE) sn -= NSTAGE;
        if (kn < KT) issue(kn, sn);
        CP_COMMIT();
        CP_WAIT(1);
        __syncthreads();
        if (++s == NSTAGE) s = 0;
    }

    // ---- epilogue ----
    #pragma unroll
    for (int nt = 0; nt < 4; nt++) {
        int col = n0 + wn + nt * 8 + (gc << 1);
        float bx = bias[col], by = bias[col + 1];
        #pragma unroll
        for (int mt = 0; mt < 4; mt++) {
            int row0 = m0 + wm + mt * 16 + gr;
            #pragma unroll
            for (int half = 0; half < 2; half++) {
                int row = row0 + half * 8;
                float vx = acc[mt][nt][half * 2 + 0] + bx;
                float vy = acc[mt][nt][half * 2 + 1] + by;
                if (EPI == 2) {
                    vx = f2tf_f(0.5f * vx * (1.0f + erff(vx * 0.70710678118654752f)));
                    vy = f2tf_f(0.5f * vy * (1.0f + erff(vy * 0.70710678118654752f)));
                }
                size_t off = (size_t)row * N + col;
                if (EPI == 1) {
                    vx += R[off];
                    vy += R[off + 1];
                }
                *(float2*)(Cout + off) = make_float2(vx, vy);
            }
        }
    }
}

// ---------------------------------------------------------------------------
// Tensor-core causal flash attention, exact 2-pass softmax.
// CTA: 128 threads (4 warps), q-tile 64, k-tile 64, 3 CTAs/SM (69.6KB smem).
// Q fragments hoisted to registers (loaded once). Pass 1 ping-pongs K;
// pass 2 double-buffers K AND V via cp.async — loads overlap mma.
// PV A-fragments via intra-quad shuffle transpose (no P smem).
// ---------------------------------------------------------------------------
#define PAD 68
#define TILE_U32 (64 * PAD)
#define ATTN_SMEM_BYTES (4 * TILE_U32 * 4)   // 69632 B

__global__ void __launch_bounds__(128, 3) attn_tc(
    const float* __restrict__ qkv, float* __restrict__ att,
    float* __restrict__ y, int write_att)
{
    extern __shared__ uint32_t sm[];
    uint32_t* B0 = sm;                 // K ping
    uint32_t* B1 = B0 + TILE_U32;      // K pong
    uint32_t* B2 = B1 + TILE_U32;      // V ping (Q staging at start)
    uint32_t* B3 = B2 + TILE_U32;      // V pong

    const int qt = gridDim.x - 1 - blockIdx.x;   // heaviest tiles first
    const int bh = blockIdx.y;
    const int b = bh >> 4, h = bh & 15;
    const int tid = threadIdx.x;
    const int lane = tid & 31, w = tid >> 5;
    const int gr = lane >> 2, gc = lane & 3;
    const int q0 = qt * 64;
    const int rs = 3 * C_;
    const float* base = qkv + (size_t)b * T_ * rs + h * DH_;
    const float scale = 0.125f;

    // cp.async tile loader: 64 rows x 64 floats, 8 cp16 per thread
    auto issueT = [&](const float* src_base, int kt, uint32_t* buf) {
        uint32_t bu = (uint32_t)__cvta_generic_to_shared(buf);
        #pragma unroll
        for (int i = 0; i < 8; i++) {
            int id = tid + i * 128;
            int row = id >> 4, c4 = id & 15;
            cp16(bu + (uint32_t)(row * PAD + c4 * 4) * 4,
                 src_base + (size_t)(kt * 64 + row) * rs + c4 * 4);
        }
    };

    const int mrowA = w * 16 + gr;

    // ---- stage Q through B2, hoist fragments into registers ----
    #pragma unroll
    for (int rr = 0; rr < 4; rr++) {
        int lin = tid + rr * 128;
        int row = lin >> 3, d4 = (lin & 7) * 8;
        float4 v0 = *(const float4*)(base + (size_t)(q0 + row) * rs + d4);
        float4 v1 = *(const float4*)(base + (size_t)(q0 + row) * rs + d4 + 4);
        *(uint4*)&B2[row * PAD + d4]     = *(uint4*)&v0;
        *(uint4*)&B2[row * PAD + d4 + 4] = *(uint4*)&v1;
    }
    __syncthreads();
    uint32_t qf[8][4];
    #pragma unroll
    for (int s8 = 0; s8 < 8; s8++) {
        int ks = s8 * 8;
        qf[s8][0] = B2[(mrowA)     * PAD + ks + gc];
        qf[s8][1] = B2[(mrowA + 8) * PAD + ks + gc];
        qf[s8][2] = B2[(mrowA)     * PAD + ks + gc + 4];
        qf[s8][3] = B2[(mrowA + 8) * PAD + ks + gc + 4];
    }
    __syncthreads();   // everyone done reading B2 before pass-2 reuses it

    float m0 = -1e30f, m1 = -1e30f, l0 = 0.f, l1 = 0.f;

    // ================= PASS 1: row statistics =================
    issueT(base + C_, 0, B0); CP_COMMIT(); CP_WAIT(0);
    __syncthreads();

    for (int kt = 0; kt <= qt; kt++) {
        const uint32_t* kb = (kt & 1) ? B1 : B0;
        if (kt < qt) { issueT(base + C_, kt + 1, (kt & 1) ? B0 : B1); CP_COMMIT(); }

        float sf[8][4];
        #pragma unroll
        for (int nf = 0; nf < 8; nf++)
            #pragma unroll
            for (int i = 0; i < 4; i++) sf[nf][i] = 0.f;

        #pragma unroll
        for (int s8 = 0; s8 < 8; s8++) {
            int ks = s8 * 8;
            #pragma unroll
            for (int nf = 0; nf < 8; nf++) {
                uint32_t bf[2];
                bf[0] = kb[(nf * 8 + gr) * PAD + ks + gc];
                bf[1] = kb[(nf * 8 + gr) * PAD + ks + gc + 4];
                mma_tf32(sf[nf], qf[s8], bf);
            }
        }

        bool diag = (kt == qt);
        #pragma unroll
        for (int nf = 0; nf < 8; nf++)
            #pragma unroll
            for (int i = 0; i < 4; i++) {
                float v = sf[nf][i] * scale;
                int ml = mrowA + ((i >= 2) ? 8 : 0);
                int nl = nf * 8 + 2 * gc + (i & 1);
                if (diag && nl > ml) v = -1e30f;
                sf[nf][i] = v;
            }

        float tm0 = -1e30f, tm1 = -1e30f;
        #pragma unroll
        for (int nf = 0; nf < 8; nf++) {
            tm0 = fmaxf(tm0, fmaxf(sf[nf][0], sf[nf][1]));
            tm1 = fmaxf(tm1, fmaxf(sf[nf][2], sf[nf][3]));
        }
        tm0 = fmaxf(tm0, __shfl_xor_sync(0xffffffffu, tm0, 1));
        tm0 = fmaxf(tm0, __shfl_xor_sync(0xffffffffu, tm0, 2));
        tm1 = fmaxf(tm1, __shfl_xor_sync(0xffffffffu, tm1, 1));
        tm1 = fmaxf(tm1, __shfl_xor_sync(0xffffffffu, tm1, 2));
        float mn0 = fmaxf(m0, tm0), mn1 = fmaxf(m1, tm1);
        float s0 = 0.f, s1 = 0.f;
        #pragma unroll
        for (int nf = 0; nf < 8; nf++) {
            s0 += __expf(sf[nf][0] - mn0) + __expf(sf[nf][1] - mn0);
            s1 += __expf(sf[nf][2] - mn1) + __expf(sf[nf][3] - mn1);
        }
        s0 += __shfl_xor_sync(0xffffffffu, s0, 1);
        s0 += __shfl_xor_sync(0xffffffffu, s0, 2);
        s1 += __shfl_xor_sync(0xffffffffu, s1, 1);
        s1 += __shfl_xor_sync(0xffffffffu, s1, 2);
        l0 = l0 * __expf(m0 - mn0) + s0; m0 = mn0;
        l1 = l1 * __expf(m1 - mn1) + s1; m1 = mn1;

        CP_WAIT(0);
        __syncthreads();
    }

    float linv0 = 1.f / l0, linv1 = 1.f / l1;

    float yac[8][4];
    #pragma unroll
    for (int nf = 0; nf < 8; nf++)
        #pragma unroll
        for (int i = 0; i < 4; i++) yac[nf][i] = 0.f;

    // ================= PASS 2: att + y = P@V (double-buffered) =================
    issueT(base + C_,     0, B0);
    issueT(base + 2 * C_, 0, B2);
    CP_COMMIT();

    for (int kt = 0; kt <= qt; kt++) {
        const uint32_t* kb = (kt & 1) ? B1 : B0;
        const uint32_t* vb = (kt & 1) ? B3 : B2;
        if (kt < qt) {
            issueT(base + C_,     kt + 1, (kt & 1) ? B0 : B1);
            issueT(base + 2 * C_, kt + 1, (kt & 1) ? B2 : B3);
            CP_COMMIT();
            CP_WAIT(1);
        } else {
            CP_WAIT(0);
        }
        __syncthreads();   // tile kt ready

        float sf[8][4];
        #pragma unroll
        for (int nf = 0; nf < 8; nf++)
            #pragma unroll
            for (int i = 0; i < 4; i++) sf[nf][i] = 0.f;

        #pragma unroll
        for (int s8 = 0; s8 < 8; s8++) {
            int ks = s8 * 8;
            #pragma unroll
            for (int nf = 0; nf < 8; nf++) {
                uint32_t bf[2];
                bf[0] = kb[(nf * 8 + gr) * PAD + ks + gc];
                bf[1] = kb[(nf * 8 + gr) * PAD + ks + gc + 4];
                mma_tf32(sf[nf], qf[s8], bf);
            }
        }

        bool diag = (kt == qt);
        #pragma unroll
        for (int j = 0; j < 8; j++) {
            float p[4];
            #pragma unroll
            for (int i = 0; i < 4; i++) {
                int ml = mrowA + ((i >= 2) ? 8 : 0);
                int nl = j * 8 + 2 * gc + (i & 1);
                float mm = (i >= 2) ? m1 : m0;
                float li = (i >= 2) ? linv1 : linv0;
                float pv = __expf(sf[j][i] * scale - mm) * li;
                if (diag && nl > ml) pv = 0.f;
                p[i] = pv;
            }
            if (write_att) {
                size_t rb = ((size_t)bh * T_ + q0 + mrowA) * T_ + kt * 64 + j * 8 + 2 * gc;
                __stcs((float2*)(att + rb),          make_float2(p[0], p[1]));
                __stcs((float2*)(att + rb + 8 * T_), make_float2(p[2], p[3]));
            }
            // shuffle transpose: accumulator layout -> A-operand layout for chunk j
            int src0 = (lane & ~3) | (gc >> 1);
            float q0v = __shfl_sync(0xffffffffu, p[0], src0);
            float q1v = __shfl_sync(0xffffffffu, p[1], src0);
            float q2v = __shfl_sync(0xffffffffu, p[2], src0);
            float q3v = __shfl_sync(0xffffffffu, p[3], src0);
            float r0v = __shfl_sync(0xffffffffu, p[0], src0 + 2);
            float r1v = __shfl_sync(0xffffffffu, p[1], src0 + 2);
            float r2v = __shfl_sync(0xffffffffu, p[2], src0 + 2);
            float r3v = __shfl_sync(0xffffffffu, p[3], src0 + 2);
            bool odd = (gc & 1);
            uint32_t af[4];
            af[0] = __float_as_uint(odd ? q1v : q0v);
            af[1] = __float_as_uint(odd ? q3v : q2v);
            af[2] = __float_as_uint(odd ? r1v : r0v);
            af[3] = __float_as_uint(odd ? r3v : r2v);
            #pragma unroll
            for (int nf2 = 0; nf2 < 8; nf2++) {
                uint32_t bf[2];
                bf[0] = vb[(j * 8 + gc)     * PAD + nf2 * 8 + gr];
                bf[1] = vb[(j * 8 + gc + 4) * PAD + nf2 * 8 + gr];
                mma_tf32(yac[nf2], af, bf);
            }
        }
        __syncthreads();   // done reading kt's buffers before next prefetch lands
    }

    // ---- zero-fill causal upper triangle ----
    if (write_att) {
        float4 z = make_float4(0.f, 0.f, 0.f, 0.f);
        for (int kt = qt + 1; kt < T_ / 64; kt++) {
            #pragma unroll
            for (int rr = 0; rr < 8; rr++) {
                int lin = tid + rr * 128;
                int row = lin >> 4, c4 = (lin & 15) * 4;
                __stcs((float4*)(att + ((size_t)bh * T_ + q0 + row) * T_ + kt * 64 + c4), z);
            }
        }
    }

    // ---- write y (tf32-rounded; feeds GEMM A operand) ----
    #pragma unroll
    for (int nf = 0; nf < 8; nf++) {
        size_t rb = ((size_t)b * T_ + q0 + mrowA) * C_ + h * DH_ + nf * 8 + 2 * gc;
        *(float2*)(y + rb)          = make_float2(f2tf_f(yac[nf][0]), f2tf_f(yac[nf][1]));
        *(float2*)(y + rb + 8 * C_) = make_float2(f2tf_f(yac[nf][2]), f2tf_f(yac[nf][3]));
    }
}

// ---------------------------------------------------------------------------
extern "C" void kernel_launch(void* const* d_in, const int* in_sizes, int n_in,
                              void* d_out, int out_size)
{
    (void)in_sizes; (void)n_in;
    const float* x      = (const float*)d_in[0];
    const float* W_attn = (const float*)d_in[1];
    const float* b_attn = (const float*)d_in[2];
    const float* W_o    = (const float*)d_in[3];
    const float* b_o    = (const float*)d_in[4];
    const float* W_fc   = (const float*)d_in[5];
    const float* b_fc   = (const float*)d_in[6];
    const float* W_fc2  = (const float*)d_in[7];
    const float* b_fc2  = (const float*)d_in[8];
    const float* g1     = (const float*)d_in[9];
    const float* be1    = (const float*)d_in[10];
    const float* g2     = (const float*)d_in[11];
    const float* be2    = (const float*)d_in[12];
    float* out = (float*)d_out;

    float *h, *qkv, *y, *x1, *m, *wa, *wo, *wf, *wf2;
    cudaGetSymbolAddress((void**)&h,   g_h);
    cudaGetSymbolAddress((void**)&qkv, g_qkv);
    cudaGetSymbolAddress((void**)&y,   g_y);
    cudaGetSymbolAddress((void**)&x1,  g_x1);
    cudaGetSymbolAddress((void**)&m,   g_m);
    cudaGetSymbolAddress((void**)&wa,  g_wattn);
    cudaGetSymbolAddress((void**)&wo,  g_wo);
    cudaGetSymbolAddress((void**)&wf,  g_wfc);
    cudaGetSymbolAddress((void**)&wf2, g_wfc2);

    int write_att = (out_size >= X_SIZE + ATT_SIZE) ? 1 : 0;
    float* att = out + X_SIZE;

    cudaFuncSetAttribute(gemm_tc<0>, cudaFuncAttributeMaxDynamicSharedMemorySize, GEMM_SMEM_BYTES);
    cudaFuncSetAttribute(gemm_tc<1>, cudaFuncAttributeMaxDynamicSharedMemorySize, GEMM_SMEM_BYTES);
    cudaFuncSetAttribute(gemm_tc<2>, cudaFuncAttributeMaxDynamicSharedMemorySize, GEMM_SMEM_BYTES);
    cudaFuncSetAttribute(attn_tc, cudaFuncAttributeMaxDynamicSharedMemorySize, ATTN_SMEM_BYTES);

    // 0. pre-round weights to tf32 (rna)
    cvt_all_kernel<<<1184, 256>>>((const float4*)W_attn, (const float4*)W_o,
                                  (const float4*)W_fc, (const float4*)W_fc2,
                                  (float4*)wa, (float4*)wo, (float4*)wf, (float4*)wf2);

    // 1. h = LN1(x)
    ln_kernel<<<BT_, 256>>>(x, g1, be1, h);
    // 2. qkv = h @ W_attn + b_attn
    gemm_tc<0><<<dim3(3 * C_ / 128, BT_ / 128), 256, GEMM_SMEM_BYTES>>>(h, wa, b_attn, nullptr, qkv, BT_, 3 * C_, C_);
    // 3. attention -> att (d_out) + y
    attn_tc<<<dim3(T_ / 64, B_ * H_), 128, ATTN_SMEM_BYTES>>>(qkv, att, y, write_att);
    // 4. x1 = x + y @ W_o + b_o
    gemm_tc<1><<<dim3(C_ / 128, BT_ / 128), 256, GEMM_SMEM_BYTES>>>(y, wo, b_o, x, x1, BT_, C_, C_);
    // 5. h = LN2(x1)
    ln_kernel<<<BT_, 256>>>(x1, g2, be2, h);
    // 6. m = gelu(h @ W_fc + b_fc)
    gemm_tc<2><<<dim3(4 * C_ / 128, BT_ / 128), 256, GEMM_SMEM_BYTES>>>(h, wf, b_fc, nullptr, m, BT_, 4 * C_, C_);
    // 7. out_x = x1 + m @ W_fc2 + b_fc2
    gemm_tc<1><<<dim3(C_ / 128, BT_ / 128), 256, GEMM_SMEM_BYTES>>>(m, wf2, b_fc2, x1, out, BT_, C_, 4 * C_);
}